// round 5
// baseline (speedup 1.0000x reference)
#include <cuda_runtime.h>

#define KTAGS 48
#define TLEN 1024
#define STOPID 47
#define NEGV (-10000.0f)

__device__ __forceinline__ unsigned long long pk2(float lo, float hi) {
    unsigned long long r;
    asm("mov.b64 %0, {%1, %2};" : "=l"(r) : "f"(lo), "f"(hi));
    return r;
}
__device__ __forceinline__ void upk2(unsigned long long v, float& lo, float& hi) {
    asm("mov.b64 {%0, %1}, %2;" : "=f"(lo), "=f"(hi) : "l"(v));
}
// d = a*b + d  (packed f32x2 -> SASS FFMA2)
__device__ __forceinline__ void fma2(unsigned long long& d, unsigned long long a, unsigned long long b) {
    asm("fma.rn.f32x2 %0, %1, %2, %0;" : "+l"(d) : "l"(a), "l"(b));
}
__device__ __forceinline__ void add2(unsigned long long& d, unsigned long long a) {
    asm("add.rn.f32x2 %0, %0, %1;" : "+l"(d) : "l"(a));
}

__global__ __launch_bounds__(32, 1)
void CRF_29265907155259_kernel(const float* __restrict__ h_tag,
                               const float* __restrict__ mask,
                               const float* __restrict__ trans,
                               float* __restrict__ out, int B)
{
    __shared__ __align__(16) float vbuf[2][2][KTAGS];   // [batch][pingpong][tag]
    const int lane = threadIdx.x;
    const int b0 = blockIdx.x * 2;
    if (b0 >= B) return;
    const int b1 = (b0 + 1 < B) ? (b0 + 1) : (B - 1);   // duplicate tail batch if odd

    const int tagA = lane;                 // rows 0..31, full j
    const int rowB = 32 + (lane & 15);     // rows 32..47, split j across half-warps
    const bool loB = (lane < 16);
    const int cbB = loB ? 0 : 24;          // j base for B split
    const int pB2 = loB ? 0 : 6;           // ulonglong2 pair-of-pair index base

    // ---- precompute E = exp(trans) in registers ----
    unsigned long long EA2[24], EB2[12];
    float rowsumA = 0.f, rowsumBp = 0.f;
    #pragma unroll
    for (int k = 0; k < 24; ++k) {
        float a0 = __expf(trans[tagA * KTAGS + 2 * k]);
        float a1 = __expf(trans[tagA * KTAGS + 2 * k + 1]);
        rowsumA += a0 + a1;
        EA2[k] = pk2(a0, a1);
    }
    #pragma unroll
    for (int k = 0; k < 12; ++k) {
        float e0 = __expf(trans[rowB * KTAGS + cbB + 2 * k]);
        float e1 = __expf(trans[rowB * KTAGS + cbB + 2 * k + 1]);
        rowsumBp += e0 + e1;
        EB2[k] = pk2(e0, e1);
    }
    const float rowsumB = rowsumBp + __shfl_xor_sync(0xffffffffu, rowsumBp, 16);
    const float EfinA = __expf(trans[STOPID * KTAGS + tagA]);
    const float EfinB = loB ? __expf(trans[STOPID * KTAGS + rowB]) : 0.f; // upper half would double-count

    const float* eb[2] = { h_tag + (size_t)b0 * TLEN * KTAGS,
                           h_tag + (size_t)b1 * TLEN * KTAGS };
    const float* mb[2] = { mask + (size_t)b0 * TLEN,
                           mask + (size_t)b1 * TLEN };

    float vA[2], vB[2];
    double M[2];

    // ---- special step t = 0 (log domain, exact) ----
    #pragma unroll
    for (int bi = 0; bi < 2; ++bi) {
        float m0 = mb[bi][0];
        float e0A = eb[bi][lane];
        float e0B = eb[bi][32 + (lane & 15)];
        float sA = NEGV + __logf(1.0f + rowsumA) + e0A;
        float sB = NEGV + __logf(1.0f + rowsumB) + e0B;
        sA = (m0 != 0.f) ? sA : NEGV;                            // rows 0..31: never STOP
        sB = (m0 != 0.f) ? sB : ((rowB == STOPID) ? 0.f : NEGV);
        float loc = fmaxf(sA, sB);
        #pragma unroll
        for (int o = 16; o; o >>= 1)
            loc = fmaxf(loc, __shfl_xor_sync(0xffffffffu, loc, o));
        M[bi] = (double)loc;
        vA[bi] = __expf(sA - loc);
        vB[bi] = __expf(sB - loc);
        vbuf[bi][0][lane] = vA[bi];
        if (loB) vbuf[bi][0][32 + lane] = vB[bi];
    }

    // ---- emit/mask prefetch, one 4-step group ahead ----
    float nA[2][4], nB[2][4], nM[2][4];
    #pragma unroll
    for (int bi = 0; bi < 2; ++bi)
        #pragma unroll
        for (int u = 0; u < 4; ++u) {
            int t = 1 + u;
            nA[bi][u] = eb[bi][t * KTAGS + lane];
            nB[bi][u] = eb[bi][t * KTAGS + 32 + (lane & 15)];
            nM[bi][u] = mb[bi][t];
        }

    int pp = 0;
    for (int base = 1; base < TLEN; base += 4) {
        float cA[2][4], cB[2][4], cM[2][4];
        #pragma unroll
        for (int bi = 0; bi < 2; ++bi)
            #pragma unroll
            for (int u = 0; u < 4; ++u) {
                cA[bi][u] = nA[bi][u]; cB[bi][u] = nB[bi][u]; cM[bi][u] = nM[bi][u];
            }
        #pragma unroll
        for (int bi = 0; bi < 2; ++bi)
            #pragma unroll
            for (int u = 0; u < 4; ++u) {
                int t = base + 4 + u;
                int tc = (t < TLEN) ? t : (TLEN - 1);
                nA[bi][u] = eb[bi][tc * KTAGS + lane];
                nB[bi][u] = eb[bi][tc * KTAGS + 32 + (lane & 15)];
                nM[bi][u] = mb[bi][tc];
            }

        #pragma unroll
        for (int u = 0; u < 4; ++u) {
            int t = base + u;
            if (t >= TLEN) break;

            float eEA0 = __expf(cA[0][u]);
            float eEB0 = __expf(cB[0][u]);
            float eEA1 = __expf(cA[1][u]);
            float eEB1 = __expf(cB[1][u]);

            __syncwarp();
            const ulonglong2* vp0 = (const ulonglong2*)&vbuf[0][pp][0];
            const ulonglong2* vp1 = (const ulonglong2*)&vbuf[1][pp][0];

            unsigned long long aA0[4] = {0,0,0,0}, aA1[4] = {0,0,0,0};
            unsigned long long aB0[2] = {0,0},     aB1[2] = {0,0};

            // A rows: full-j dot, both batches interleaved (broadcast LDS.128)
            #pragma unroll
            for (int k2 = 0; k2 < 12; ++k2) {
                ulonglong2 w0 = vp0[k2];
                ulonglong2 w1 = vp1[k2];
                fma2(aA0[(2 * k2) % 4],     EA2[2 * k2],     w0.x);
                fma2(aA0[(2 * k2 + 1) % 4], EA2[2 * k2 + 1], w0.y);
                fma2(aA1[(2 * k2) % 4],     EA2[2 * k2],     w1.x);
                fma2(aA1[(2 * k2 + 1) % 4], EA2[2 * k2 + 1], w1.y);
            }
            // B rows: half-j per half-warp (2-way address split, then shfl merge)
            #pragma unroll
            for (int k2 = 0; k2 < 6; ++k2) {
                ulonglong2 w0 = vp0[pB2 + k2];
                ulonglong2 w1 = vp1[pB2 + k2];
                fma2(aB0[0], EB2[2 * k2],     w0.x);
                fma2(aB0[1], EB2[2 * k2 + 1], w0.y);
                fma2(aB1[0], EB2[2 * k2],     w1.x);
                fma2(aB1[1], EB2[2 * k2 + 1], w1.y);
            }

            add2(aA0[0], aA0[2]); add2(aA0[1], aA0[3]); add2(aA0[0], aA0[1]);
            add2(aA1[0], aA1[2]); add2(aA1[1], aA1[3]); add2(aA1[0], aA1[1]);
            add2(aB0[0], aB0[1]);
            add2(aB1[0], aB1[1]);

            float l0, h0, l1, h1;
            upk2(aA0[0], l0, h0); float dotA0 = l0 + h0;
            upk2(aA1[0], l1, h1); float dotA1 = l1 + h1;
            upk2(aB0[0], l0, h0); float pB0s = l0 + h0;
            upk2(aB1[0], l1, h1); float pB1s = l1 + h1;
            float dotB0 = pB0s + __shfl_xor_sync(0xffffffffu, pB0s, 16);
            float dotB1 = pB1s + __shfl_xor_sync(0xffffffffu, pB1s, 16);

            bool live0 = (cM[0][u] != 0.f);
            bool live1 = (cM[1][u] != 0.f);
            vA[0] = live0 ? dotA0 * eEA0 : vA[0];
            vB[0] = live0 ? dotB0 * eEB0 : vB[0];
            vA[1] = live1 ? dotA1 * eEA1 : vA[1];
            vB[1] = live1 ? dotB1 * eEB1 : vB[1];

            if ((u == 3) || (t == TLEN - 1)) {
                // all v >= 0 -> float max == uint max
                float lm0 = fmaxf(vA[0], vB[0]);
                float lm1 = fmaxf(vA[1], vB[1]);
                float mx0 = __uint_as_float(__reduce_max_sync(0xffffffffu, __float_as_uint(lm0)));
                float mx1 = __uint_as_float(__reduce_max_sync(0xffffffffu, __float_as_uint(lm1)));
                float r0 = __fdividef(1.0f, mx0);
                float r1 = __fdividef(1.0f, mx1);
                vA[0] *= r0; vB[0] *= r0;
                vA[1] *= r1; vB[1] *= r1;
                M[0] += (double)__logf(mx0);
                M[1] += (double)__logf(mx1);
            }
            int np = pp ^ 1;
            vbuf[0][np][lane] = vA[0];
            vbuf[1][np][lane] = vA[1];
            if (loB) {
                vbuf[0][np][32 + lane] = vB[0];
                vbuf[1][np][32 + lane] = vB[1];
            }
            pp = np;
        }
    }

    // ---- finalize: out = M + log(sum_i v_i * exp(trans[STOP, i])) ----
    #pragma unroll
    for (int bi = 0; bi < 2; ++bi) {
        float fin = vA[bi] * EfinA + vB[bi] * EfinB;   // EfinB = 0 on upper half (no double count)
        #pragma unroll
        for (int o = 16; o; o >>= 1)
            fin += __shfl_xor_sync(0xffffffffu, fin, o);
        if (lane == 0 && (b0 + bi) < B)
            out[b0 + bi] = (float)(M[bi] + (double)__logf(fin));
    }
}

extern "C" void kernel_launch(void* const* d_in, const int* in_sizes, int n_in,
                              void* d_out, int out_size) {
    const float* h_tag = (const float*)d_in[0];
    const float* msk   = (const float*)d_in[1];
    const float* trans = (const float*)d_in[2];
    float* out = (float*)d_out;
    int B = in_sizes[0] / (TLEN * KTAGS);
    int blocks = (B + 1) / 2;
    CRF_29265907155259_kernel<<<blocks, 32>>>(h_tag, msk, trans, out, B);
}

// round 7
// speedup vs baseline: 1.7958x; 1.7958x over previous
#include <cuda_runtime.h>

#define KTAGS 48
#define TLEN 1024
#define STOPID 47
#define NEGV (-10000.0f)

__device__ __forceinline__ unsigned long long pk2(float lo, float hi) {
    unsigned long long r;
    asm("mov.b64 %0, {%1, %2};" : "=l"(r) : "f"(lo), "f"(hi));
    return r;
}
__device__ __forceinline__ void upk2(unsigned long long v, float& lo, float& hi) {
    asm("mov.b64 {%0, %1}, %2;" : "=f"(lo), "=f"(hi) : "l"(v));
}
// d = a*b + d  (packed f32x2 -> SASS FFMA2)
__device__ __forceinline__ void fma2(unsigned long long& d, unsigned long long a, unsigned long long b) {
    asm("fma.rn.f32x2 %0, %1, %2, %0;" : "+l"(d) : "l"(a), "l"(b));
}
__device__ __forceinline__ void add2(unsigned long long& d, unsigned long long a) {
    asm("add.rn.f32x2 %0, %0, %1;" : "+l"(d) : "l"(a));
}

// One block = one batch. Warp 0: forward over emissions 0..511.
// Warp 1: backward over emissions 1023..512 with E^T.
// Z = Mf + Mb + log(sum_i alphaHat_i * betaHat_i).
__global__ __launch_bounds__(64, 1)
void CRF_29265907155259_kernel(const float* __restrict__ h_tag,
                               const float* __restrict__ mask,
                               const float* __restrict__ trans,
                               float* __restrict__ out, int B)
{
    __shared__ __align__(16) float vbuf[2][2][KTAGS];   // [warp][pingpong][tag]
    __shared__ float cbuf[2][KTAGS];
    __shared__ double Msh[2];

    const int lane = threadIdx.x & 31;
    const int warp = threadIdx.x >> 5;
    const int b = blockIdx.x;
    if (b >= B) return;
    const bool fwd = (warp == 0);

    const int tagA = lane;                 // rows 0..31, full j
    const int rowB = 32 + (lane & 15);     // rows 32..47, split j across half-warps
    const bool loB = (lane < 16);
    const int cbB = loB ? 0 : 24;          // j base for B split
    const int pB2 = loB ? 0 : 6;           // ulonglong2 index base for B split

    // ---- E = exp(trans) (fwd) or exp(trans)^T (bwd) rows in registers ----
    unsigned long long EA2[24], EB2[12];
    float rowsumA = 0.f, rowsumBp = 0.f;
    #pragma unroll
    for (int k = 0; k < 24; ++k) {
        int j0 = 2 * k, j1 = 2 * k + 1;
        float a0 = __expf(fwd ? trans[tagA * KTAGS + j0] : trans[j0 * KTAGS + tagA]);
        float a1 = __expf(fwd ? trans[tagA * KTAGS + j1] : trans[j1 * KTAGS + tagA]);
        rowsumA += a0 + a1;
        EA2[k] = pk2(a0, a1);
    }
    #pragma unroll
    for (int k = 0; k < 12; ++k) {
        int j0 = cbB + 2 * k, j1 = cbB + 2 * k + 1;
        float e0 = __expf(fwd ? trans[rowB * KTAGS + j0] : trans[j0 * KTAGS + rowB]);
        float e1 = __expf(fwd ? trans[rowB * KTAGS + j1] : trans[j1 * KTAGS + rowB]);
        rowsumBp += e0 + e1;
        EB2[k] = pk2(e0, e1);
    }
    const float rowsumB = rowsumBp + __shfl_xor_sync(0xffffffffu, rowsumBp, 16);

    const float* eb = h_tag + (size_t)b * TLEN * KTAGS;
    const float* mb = mask + (size_t)b * TLEN;

    float vA, vB;
    double M;

    if (fwd) {
        // ---- special step t = 0 (log domain, exact; exp-domain would underflow) ----
        float m0 = mb[0];
        float e0A = eb[tagA];
        float e0B = eb[rowB];
        float sA = NEGV + __logf(1.0f + rowsumA) + e0A;
        float sB = NEGV + __logf(1.0f + rowsumB) + e0B;
        sA = (m0 != 0.f) ? sA : NEGV;                            // rows 0..31: never STOP
        sB = (m0 != 0.f) ? sB : ((rowB == STOPID) ? 0.f : NEGV);
        float loc = fmaxf(sA, sB);
        #pragma unroll
        for (int o = 16; o; o >>= 1)
            loc = fmaxf(loc, __shfl_xor_sync(0xffffffffu, loc, o));
        M = (double)loc;
        vA = __expf(sA - loc);
        vB = __expf(sB - loc);
    } else {
        // beta_{1023}(i) = exp(trans[STOP, i]); values O(e^4) -> no scaling needed
        vA = __expf(trans[STOPID * KTAGS + tagA]);
        vB = __expf(trans[STOPID * KTAGS + rowB]);
        M = 0.0;
    }

    // step s -> emission index t: fwd t = s (s=1..511); bwd t = 1024-s (s=1..512)
    // ---- emit/mask prefetch, one 4-step group ahead ----
    float nA[4], nB[4], nM[4];
    #pragma unroll
    for (int u = 0; u < 4; ++u) {
        int s = 1 + u;
        int t = fwd ? s : (TLEN - s);
        nA[u] = eb[t * KTAGS + tagA];
        nB[u] = eb[t * KTAGS + rowB];
        nM[u] = mb[t];
    }

    int pp = 0;
    for (int base = 1; base < 513; base += 4) {
        float cA[4], cB[4], cM[4];
        #pragma unroll
        for (int u = 0; u < 4; ++u) { cA[u] = nA[u]; cB[u] = nB[u]; cM[u] = nM[u]; }
        #pragma unroll
        for (int u = 0; u < 4; ++u) {
            int s = base + 4 + u;                 // max 516; valid t both directions
            int t = fwd ? s : (TLEN - s);
            nA[u] = eb[t * KTAGS + tagA];
            nB[u] = eb[t * KTAGS + rowB];
            nM[u] = mb[t];
        }
        #pragma unroll
        for (int u = 0; u < 4; ++u) {
            int s = base + u;
            if (fwd && s > 511) break;            // fwd does 511 loop steps, bwd 512

            float eEA = __expf(cA[u]);
            float eEB = __expf(cB[u]);

            // fwd stores v, multiplies emission after matvec (alpha' = D E alpha)
            // bwd stores v*exp(e), matvec only (beta' = E^T D beta)
            float wA = fwd ? vA : vA * eEA;
            float wB = fwd ? vB : vB * eEB;
            vbuf[warp][pp][lane] = wA;
            if (loB) vbuf[warp][pp][32 + lane] = wB;
            __syncwarp();

            const ulonglong2* vp = (const ulonglong2*)&vbuf[warp][pp][0];
            unsigned long long aA[4] = {0, 0, 0, 0};
            unsigned long long aB[2] = {0, 0};
            // A rows: full-j dot (broadcast LDS.128)
            #pragma unroll
            for (int k2 = 0; k2 < 12; ++k2) {
                ulonglong2 w = vp[k2];
                fma2(aA[(2 * k2) % 4],     EA2[2 * k2],     w.x);
                fma2(aA[(2 * k2 + 1) % 4], EA2[2 * k2 + 1], w.y);
            }
            // B rows: half-j per half-warp, shfl merge
            #pragma unroll
            for (int k2 = 0; k2 < 6; ++k2) {
                ulonglong2 w = vp[pB2 + k2];
                fma2(aB[0], EB2[2 * k2],     w.x);
                fma2(aB[1], EB2[2 * k2 + 1], w.y);
            }
            add2(aA[0], aA[2]); add2(aA[1], aA[3]); add2(aA[0], aA[1]);
            add2(aB[0], aB[1]);

            float l0, h0;
            upk2(aA[0], l0, h0); float dotA = l0 + h0;
            upk2(aB[0], l0, h0); float pBs = l0 + h0;
            float dotB = pBs + __shfl_xor_sync(0xffffffffu, pBs, 16);

            float rawA = fwd ? dotA * eEA : dotA;
            float rawB = fwd ? dotB * eEB : dotB;
            bool live = (cM[u] != 0.f);
            vA = live ? rawA : vA;
            vB = live ? rawB : vB;

            if ((u == 3) || (fwd && s == 511)) {
                // all v >= 0 -> float max == uint max
                float lmax = fmaxf(vA, vB);
                float mx = __uint_as_float(__reduce_max_sync(0xffffffffu, __float_as_uint(lmax)));
                float r = __fdividef(1.0f, mx);
                vA *= r;
                vB *= r;
                M += (double)__logf(mx);
            }
            pp ^= 1;
        }
    }

    // ---- combine: Z = Mf + Mb + log(sum_i alpha_i * beta_i) ----
    cbuf[warp][lane] = vA;
    if (loB) cbuf[warp][32 + lane] = vB;
    if (lane == 0) Msh[warp] = M;
    __syncthreads();

    if (warp == 0) {
        float fin = cbuf[0][lane] * cbuf[1][lane];
        if (loB) fin += cbuf[0][32 + lane] * cbuf[1][32 + lane];
        #pragma unroll
        for (int o = 16; o; o >>= 1)
            fin += __shfl_xor_sync(0xffffffffu, fin, o);
        if (lane == 0)
            out[b] = (float)(Msh[0] + Msh[1] + (double)__logf(fin));
    }
}

extern "C" void kernel_launch(void* const* d_in, const int* in_sizes, int n_in,
                              void* d_out, int out_size) {
    const float* h_tag = (const float*)d_in[0];
    const float* msk   = (const float*)d_in[1];
    const float* trans = (const float*)d_in[2];
    float* out = (float*)d_out;
    int B = in_sizes[0] / (TLEN * KTAGS);
    CRF_29265907155259_kernel<<<B, 64>>>(h_tag, msk, trans, out, B);
}

// round 8
// speedup vs baseline: 1.8230x; 1.0152x over previous
#include <cuda_runtime.h>

#define KTAGS 48
#define TLEN 1024
#define STOPID 47
#define NEGV (-10000.0f)

__device__ __forceinline__ unsigned long long pk2(float lo, float hi) {
    unsigned long long r;
    asm("mov.b64 %0, {%1, %2};" : "=l"(r) : "f"(lo), "f"(hi));
    return r;
}
__device__ __forceinline__ void upk2(unsigned long long v, float& lo, float& hi) {
    asm("mov.b64 {%0, %1}, %2;" : "=f"(lo), "=f"(hi) : "l"(v));
}
// d = a*b + d  (packed f32x2 -> SASS FFMA2)
__device__ __forceinline__ void fma2(unsigned long long& d, unsigned long long a, unsigned long long b) {
    asm("fma.rn.f32x2 %0, %1, %2, %0;" : "+l"(d) : "l"(a), "l"(b));
}
__device__ __forceinline__ void add2(unsigned long long& d, unsigned long long a) {
    asm("add.rn.f32x2 %0, %0, %1;" : "+l"(d) : "l"(a));
}

// One block = 4 batches, 8 warps. Warp w: batch blk*4 + (w>>1), fwd if (w&1)==0.
// Warp->SMSP map (wid%4) covers all 4 SMSPs: 2 warps per SMSP.
// fwd: alpha over emissions 0..511.  bwd: beta over emissions 1023..512 with E^T.
// Z = Mf + Mb + log(sum_i alphaHat_i * betaHat_i).
__global__ __launch_bounds__(256, 1)
void CRF_29265907155259_kernel(const float* __restrict__ h_tag,
                               const float* __restrict__ mask,
                               const float* __restrict__ trans,
                               float* __restrict__ out, int B)
{
    __shared__ __align__(16) float vbuf[8][2][KTAGS];   // [warp][pingpong][tag]
    __shared__ float cbuf[8][KTAGS];
    __shared__ double Msh[8];

    const int lane = threadIdx.x & 31;
    const int warp = threadIdx.x >> 5;
    const bool fwd = ((warp & 1) == 0);
    int b = blockIdx.x * 4 + (warp >> 1);
    bool valid = (b < B);
    if (!valid) b = B - 1;                 // clamp (duplicate work) so __syncthreads is safe

    const int tagA = lane;                 // rows 0..31, full j
    const int rowB = 32 + (lane & 15);     // rows 32..47, split j across half-warps
    const bool loB = (lane < 16);
    const int cbB = loB ? 0 : 24;          // j base for B split
    const int pB2 = loB ? 0 : 6;           // ulonglong2 index base for B split

    // ---- E = exp(trans) (fwd) or exp(trans)^T (bwd) rows in registers ----
    unsigned long long EA2[24], EB2[12];
    float rowsumA = 0.f, rowsumBp = 0.f;
    #pragma unroll
    for (int k = 0; k < 24; ++k) {
        int j0 = 2 * k, j1 = 2 * k + 1;
        float a0 = __expf(fwd ? trans[tagA * KTAGS + j0] : trans[j0 * KTAGS + tagA]);
        float a1 = __expf(fwd ? trans[tagA * KTAGS + j1] : trans[j1 * KTAGS + tagA]);
        rowsumA += a0 + a1;
        EA2[k] = pk2(a0, a1);
    }
    #pragma unroll
    for (int k = 0; k < 12; ++k) {
        int j0 = cbB + 2 * k, j1 = cbB + 2 * k + 1;
        float e0 = __expf(fwd ? trans[rowB * KTAGS + j0] : trans[j0 * KTAGS + rowB]);
        float e1 = __expf(fwd ? trans[rowB * KTAGS + j1] : trans[j1 * KTAGS + rowB]);
        rowsumBp += e0 + e1;
        EB2[k] = pk2(e0, e1);
    }
    const float rowsumB = rowsumBp + __shfl_xor_sync(0xffffffffu, rowsumBp, 16);

    const float* eb = h_tag + (size_t)b * TLEN * KTAGS;
    const float* mb = mask + (size_t)b * TLEN;

    float vA, vB;
    double M;

    if (fwd) {
        // ---- special step t = 0 (log domain, exact; exp-domain would underflow) ----
        float m0 = mb[0];
        float e0A = eb[tagA];
        float e0B = eb[rowB];
        float sA = NEGV + __logf(1.0f + rowsumA) + e0A;
        float sB = NEGV + __logf(1.0f + rowsumB) + e0B;
        sA = (m0 != 0.f) ? sA : NEGV;                            // rows 0..31: never STOP
        sB = (m0 != 0.f) ? sB : ((rowB == STOPID) ? 0.f : NEGV);
        float loc = fmaxf(sA, sB);
        #pragma unroll
        for (int o = 16; o; o >>= 1)
            loc = fmaxf(loc, __shfl_xor_sync(0xffffffffu, loc, o));
        M = (double)loc;
        vA = __expf(sA - loc);
        vB = __expf(sB - loc);
    } else {
        // beta_{1023}(i) = exp(trans[STOP, i]); values O(e^4) -> no scaling needed
        vA = __expf(trans[STOPID * KTAGS + tagA]);
        vB = __expf(trans[STOPID * KTAGS + rowB]);
        M = 0.0;
    }

    // step s -> emission index t: fwd t = s (s=1..511); bwd t = 1024-s (s=1..512)
    // ---- emit/mask prefetch, one 4-step group ahead ----
    float nA[4], nB[4], nM[4];
    #pragma unroll
    for (int u = 0; u < 4; ++u) {
        int s = 1 + u;
        int t = fwd ? s : (TLEN - s);
        nA[u] = eb[t * KTAGS + tagA];
        nB[u] = eb[t * KTAGS + rowB];
        nM[u] = mb[t];
    }

    int pp = 0;
    for (int base = 1; base < 513; base += 4) {
        float cA[4], cB[4], cM[4];
        #pragma unroll
        for (int u = 0; u < 4; ++u) { cA[u] = nA[u]; cB[u] = nB[u]; cM[u] = nM[u]; }
        #pragma unroll
        for (int u = 0; u < 4; ++u) {
            int s = base + 4 + u;                 // max 516; t valid both directions
            int t = fwd ? s : (TLEN - s);
            nA[u] = eb[t * KTAGS + tagA];
            nB[u] = eb[t * KTAGS + rowB];
            nM[u] = mb[t];
        }
        #pragma unroll
        for (int u = 0; u < 4; ++u) {
            int s = base + u;
            if (fwd && s > 511) break;            // fwd: 511 loop steps; bwd: 512

            float eEA = __expf(cA[u]);
            float eEB = __expf(cB[u]);

            // fwd stores v, multiplies emission after matvec (alpha' = D E alpha)
            // bwd stores v*exp(e), matvec only (beta' = E^T D beta)
            float wA = fwd ? vA : vA * eEA;
            float wB = fwd ? vB : vB * eEB;
            vbuf[warp][pp][lane] = wA;
            if (loB) vbuf[warp][pp][32 + lane] = wB;
            __syncwarp();

            const ulonglong2* vp = (const ulonglong2*)&vbuf[warp][pp][0];
            unsigned long long aA[4] = {0, 0, 0, 0};
            unsigned long long aB[2] = {0, 0};
            // A rows: full-j dot (broadcast LDS.128)
            #pragma unroll
            for (int k2 = 0; k2 < 12; ++k2) {
                ulonglong2 w = vp[k2];
                fma2(aA[(2 * k2) % 4],     EA2[2 * k2],     w.x);
                fma2(aA[(2 * k2 + 1) % 4], EA2[2 * k2 + 1], w.y);
            }
            // B rows: half-j per half-warp, shfl merge
            #pragma unroll
            for (int k2 = 0; k2 < 6; ++k2) {
                ulonglong2 w = vp[pB2 + k2];
                fma2(aB[0], EB2[2 * k2],     w.x);
                fma2(aB[1], EB2[2 * k2 + 1], w.y);
            }
            add2(aA[0], aA[2]); add2(aA[1], aA[3]); add2(aA[0], aA[1]);
            add2(aB[0], aB[1]);

            float l0, h0;
            upk2(aA[0], l0, h0); float dotA = l0 + h0;
            upk2(aB[0], l0, h0); float pBs = l0 + h0;
            float dotB = pBs + __shfl_xor_sync(0xffffffffu, pBs, 16);

            float rawA = fwd ? dotA * eEA : dotA;
            float rawB = fwd ? dotB * eEB : dotB;
            bool live = (cM[u] != 0.f);
            vA = live ? rawA : vA;
            vB = live ? rawB : vB;

            if ((u == 3) || (fwd && s == 511)) {
                // all v >= 0 -> float max == uint max
                float lmax = fmaxf(vA, vB);
                float mx = __uint_as_float(__reduce_max_sync(0xffffffffu, __float_as_uint(lmax)));
                float r = __fdividef(1.0f, mx);
                vA *= r;
                vB *= r;
                M += (double)__logf(mx);
            }
            pp ^= 1;
        }
    }

    // ---- combine: Z = Mf + Mb + log(sum_i alpha_i * beta_i) ----
    cbuf[warp][lane] = vA;
    if (loB) cbuf[warp][32 + lane] = vB;
    if (lane == 0) Msh[warp] = M;
    __syncthreads();

    if (fwd) {
        float fin = cbuf[warp][lane] * cbuf[warp + 1][lane];
        if (loB) fin += cbuf[warp][32 + lane] * cbuf[warp + 1][32 + lane];
        #pragma unroll
        for (int o = 16; o; o >>= 1)
            fin += __shfl_xor_sync(0xffffffffu, fin, o);
        if (lane == 0 && valid)
            out[b] = (float)(Msh[warp] + Msh[warp + 1] + (double)__logf(fin));
    }
}

extern "C" void kernel_launch(void* const* d_in, const int* in_sizes, int n_in,
                              void* d_out, int out_size) {
    const float* h_tag = (const float*)d_in[0];
    const float* msk   = (const float*)d_in[1];
    const float* trans = (const float*)d_in[2];
    float* out = (float*)d_out;
    int B = in_sizes[0] / (TLEN * KTAGS);
    int blocks = (B + 3) / 4;
    CRF_29265907155259_kernel<<<blocks, 256>>>(h_tag, msk, trans, out, B);
}